// round 1
// baseline (speedup 1.0000x reference)
#include <cuda_runtime.h>
#include <math.h>

#define OUT_COLS 2883

// scratch: batch-0 features transposed to [H,W,C], concatenated per scale
//   s0: [56*56,64]  @ 0        (200704 floats)
//   s1: [28*28,128] @ 200704   (100352)
//   s2: [14*14,256] @ 301056   (50176)
//   s3: [7*7,512]   @ 351232   (25088)
__device__ float g_scratch[376320];
// consts: [0..8] Minv[d][k] (d*3+k), [9..11] o0,
//         per view v at 12+v*12: c[v][k][d] (k*3+d), then o_v at +9..+11
__device__ float g_consts[12 + 3 * 12];

__global__ void camera_kernel(const float* __restrict__ cameras) {
    if (threadIdx.x != 0 || blockIdx.x != 0) return;
    const double PIf = (double)3.14159274101257324;  // double(float32(pi))

    double cn[3][3][3];   // per view, normalized axis rows (X,Y,Z)
    double Zax[3][3];     // unnormalized Z axis = camera origin o

    for (int v = 0; v < 3; v++) {
        double th = (double)cameras[v * 5 + 0] * (PIf / 180.0);
        double ph = (double)cameras[v * 5 + 1] * (PIf / 180.0);
        double r  = (double)cameras[v * 5 + 3];
        double camy = r * sin(ph);
        double lens = r * cos(ph);
        double camx = lens * cos(th);
        double camz = lens * sin(th);
        double Z[3] = {camx, camy, camz};
        double Y[3] = {camy * cos(th + PIf), lens, camy * sin(th + PIf)};
        double X[3] = {Y[1] * Z[2] - Y[2] * Z[1],
                       Y[2] * Z[0] - Y[0] * Z[2],
                       Y[0] * Z[1] - Y[1] * Z[0]};
        double nx = sqrt(X[0]*X[0] + X[1]*X[1] + X[2]*X[2]);
        double ny = sqrt(Y[0]*Y[0] + Y[1]*Y[1] + Y[2]*Y[2]);
        double nz = sqrt(Z[0]*Z[0] + Z[1]*Z[1] + Z[2]*Z[2]);
        for (int d = 0; d < 3; d++) {
            cn[v][0][d] = X[d] / nx;
            cn[v][1][d] = Y[d] / ny;
            cn[v][2][d] = Z[d] / nz;
            Zax[v][d] = Z[d];
        }
        for (int k = 0; k < 3; k++)
            for (int d = 0; d < 3; d++)
                g_consts[12 + v * 12 + k * 3 + d] = (float)cn[v][k][d];
        for (int d = 0; d < 3; d++)
            g_consts[12 + v * 12 + 9 + d] = (float)Zax[v][d];
    }

    // A = c0^T ; Minv = inv(A)
    double A[3][3];
    for (int i = 0; i < 3; i++)
        for (int j = 0; j < 3; j++)
            A[i][j] = cn[0][j][i];
    double det = A[0][0] * (A[1][1]*A[2][2] - A[1][2]*A[2][1])
               + A[0][1] * (A[1][2]*A[2][0] - A[1][0]*A[2][2])
               + A[0][2] * (A[1][0]*A[2][1] - A[1][1]*A[2][0]);
    double inv[3][3];
    inv[0][0] = (A[1][1]*A[2][2] - A[1][2]*A[2][1]) / det;
    inv[0][1] = (A[0][2]*A[2][1] - A[0][1]*A[2][2]) / det;
    inv[0][2] = (A[0][1]*A[1][2] - A[0][2]*A[1][1]) / det;
    inv[1][0] = (A[1][2]*A[2][0] - A[1][0]*A[2][2]) / det;
    inv[1][1] = (A[0][0]*A[2][2] - A[0][2]*A[2][0]) / det;
    inv[1][2] = (A[0][2]*A[1][0] - A[0][0]*A[1][2]) / det;
    inv[2][0] = (A[1][0]*A[2][1] - A[1][1]*A[2][0]) / det;
    inv[2][1] = (A[0][1]*A[2][0] - A[0][0]*A[2][1]) / det;
    inv[2][2] = (A[0][0]*A[1][1] - A[0][1]*A[1][0]) / det;
    for (int d = 0; d < 3; d++)
        for (int k = 0; k < 3; k++)
            g_consts[d * 3 + k] = (float)inv[d][k];
    for (int d = 0; d < 3; d++)
        g_consts[9 + d] = (float)Zax[0][d];
}

__global__ void transpose_kernel(const float* __restrict__ f0,
                                 const float* __restrict__ f1,
                                 const float* __restrict__ f2,
                                 const float* __restrict__ f3) {
    int i = blockIdx.x * blockDim.x + threadIdx.x;
    if (i >= 376320) return;
    float v;
    if (i < 200704)      { int c = i & 63;  int p = i >> 6;                 v = f0[c * 3136 + p]; }
    else if (i < 301056) { int l = i - 200704; int c = l & 127; int p = l >> 7; v = f1[c * 784 + p]; }
    else if (i < 351232) { int l = i - 301056; int c = l & 255; int p = l >> 8; v = f2[c * 196 + p]; }
    else                 { int l = i - 351232; int c = l & 511; int p = l >> 9; v = f3[c * 49 + p]; }
    g_scratch[i] = v;
}

__global__ __launch_bounds__(256) void main_kernel(const float* __restrict__ inputs,
                                                   float* __restrict__ out) {
    __shared__ int sbase[3][4];
    int row = blockIdx.x;
    int tid = threadIdx.x;

    if (tid < 3) {
        int v = tid;
        float in0 = inputs[row * 3 + 0];
        float in1 = inputs[row * 3 + 1];
        float in2 = inputs[row * 3 + 2];
        const float* C = g_consts;
        float po[3];
        #pragma unroll
        for (int k = 0; k < 3; k++)
            po[k] = fmaf(in0, C[0 * 3 + k],
                    fmaf(in1, C[1 * 3 + k],
                    fmaf(in2, C[2 * 3 + k], C[9 + k])));
        const float* cv = C + 12 + v * 12;
        float d0 = po[0] - cv[9];
        float d1 = po[1] - cv[10];
        float d2 = po[2] - cv[11];
        float X = fmaf(d0, cv[0], fmaf(d1, cv[1], d2 * cv[2]));
        float Y = fmaf(d0, cv[3], fmaf(d1, cv[4], d2 * cv[5]));
        float Z = fmaf(d0, cv[6], fmaf(d1, cv[7], d2 * cv[8]));
        float nz = -Z;
        float h = fmaf(248.0f, __fdiv_rn(-Y, nz), 112.0f);
        float w = fmaf(248.0f, __fdiv_rn(X, nz), 112.0f);
        if (isnan(h)) h = 0.0f;
        if (isnan(w)) w = 0.0f;
        h = fminf(fmaxf(h, 0.0f), 223.0f);
        w = fminf(fmaxf(w, 0.0f), 223.0f);
        // exact power-of-two scaling == reference's exact divisions
        int h0 = (int)(h * 0.25f),    w0 = (int)(w * 0.25f);
        int h1 = (int)(h * 0.125f),   w1 = (int)(w * 0.125f);
        int h2 = (int)(h * 0.0625f),  w2 = (int)(w * 0.0625f);
        int h3 = (int)(h * 0.03125f), w3 = (int)(w * 0.03125f);
        sbase[v][0] = (h0 * 56 + w0) * 64;
        sbase[v][1] = 200704 + (h1 * 28 + w1) * 128;
        sbase[v][2] = 301056 + (h2 * 14 + w2) * 256;
        sbase[v][3] = 351232 + (h3 * 7 + w3) * 512;
        out[(size_t)row * OUT_COLS + v] = (v == 0) ? in0 : (v == 1) ? in1 : in2;
    }
    __syncthreads();

    int b00 = sbase[0][0], b01 = sbase[0][1], b02 = sbase[0][2], b03 = sbase[0][3];
    int b10 = sbase[1][0], b11 = sbase[1][1], b12 = sbase[1][2], b13 = sbase[1][3];
    int b20 = sbase[2][0], b21 = sbase[2][1], b22 = sbase[2][2], b23 = sbase[2][3];

    float* omax = out + (size_t)row * OUT_COLS + 3;

    #pragma unroll
    for (int it = 0; it < 4; it++) {
        int c = tid + it * 256;
        if (c >= 960) break;
        int i0, i1, i2;
        if (c < 64)       { i0 = b00 + c;       i1 = b10 + c;       i2 = b20 + c; }
        else if (c < 192) { int l = c - 64;  i0 = b01 + l; i1 = b11 + l; i2 = b21 + l; }
        else if (c < 448) { int l = c - 192; i0 = b02 + l; i1 = b12 + l; i2 = b22 + l; }
        else              { int l = c - 448; i0 = b03 + l; i1 = b13 + l; i2 = b23 + l; }
        float a = __ldg(&g_scratch[i0]);
        float b = __ldg(&g_scratch[i1]);
        float d = __ldg(&g_scratch[i2]);
        float mx = fmaxf(a, fmaxf(b, d));
        float mn = (a + b + d) * (1.0f / 3.0f);
        float e0 = a - mn, e1 = b - mn, e2 = d - mn;
        float sd = sqrtf((e0 * e0 + e1 * e1 + e2 * e2) * (1.0f / 3.0f));
        omax[c] = mx;
        omax[960 + c] = mn;
        omax[1920 + c] = sd;
    }
}

extern "C" void kernel_launch(void* const* d_in, const int* in_sizes, int n_in,
                              void* d_out, int out_size) {
    const float* inputs  = (const float*)d_in[0];
    const float* cameras = (const float*)d_in[1];
    const float* f0 = (const float*)d_in[2];
    const float* f1 = (const float*)d_in[3];
    const float* f2 = (const float*)d_in[4];
    const float* f3 = (const float*)d_in[5];
    float* out = (float*)d_out;

    int n = in_sizes[0] / 3;

    camera_kernel<<<1, 1>>>(cameras);
    transpose_kernel<<<(376320 + 255) / 256, 256>>>(f0, f1, f2, f3);
    main_kernel<<<n, 256>>>(inputs, out);
}

// round 2
// speedup vs baseline: 1.2456x; 1.2456x over previous
#include <cuda_runtime.h>
#include <math.h>

#define OUT_COLS 2883

// scratch: batch-0 features transposed to [H,W,C], concatenated per scale
//   s0: [56*56,64]  @ 0        (200704 floats)
//   s1: [28*28,128] @ 200704   (100352)
//   s2: [14*14,256] @ 301056   (50176)
//   s3: [7*7,512]   @ 351232   (25088)
__device__ float g_scratch[376320];
// consts: [0..8] Minv[d][k] (d*3+k), [9..11] o0,
//         per view v at 12+v*12: c[v][k][d] (k*3+d), then o_v at +9..+11
__device__ float g_consts[12 + 3 * 12];

// Fused: feature transpose (all blocks) + camera constants (block 0, threads 0-2)
__global__ void prep_kernel(const float* __restrict__ f0,
                            const float* __restrict__ f1,
                            const float* __restrict__ f2,
                            const float* __restrict__ f3,
                            const float* __restrict__ cameras) {
    // --- camera constants, fp32 trig matching the fp32 reference ---
    if (blockIdx.x == 0 && threadIdx.x < 3) {
        const float PIF = 3.14159274101257324f;
        int v = threadIdx.x;
        float th = cameras[v * 5 + 0] * (PIF / 180.0f);
        float ph = cameras[v * 5 + 1] * (PIF / 180.0f);
        float r  = cameras[v * 5 + 3];
        float camy = r * sinf(ph);
        float lens = r * cosf(ph);
        float camx = lens * cosf(th);
        float camz = lens * sinf(th);
        float Z[3] = {camx, camy, camz};
        float Y[3] = {camy * cosf(th + PIF), lens, camy * sinf(th + PIF)};
        float X[3] = {Y[1] * Z[2] - Y[2] * Z[1],
                      Y[2] * Z[0] - Y[0] * Z[2],
                      Y[0] * Z[1] - Y[1] * Z[0]};
        float nx = sqrtf(X[0]*X[0] + X[1]*X[1] + X[2]*X[2]);
        float ny = sqrtf(Y[0]*Y[0] + Y[1]*Y[1] + Y[2]*Y[2]);
        float nz = sqrtf(Z[0]*Z[0] + Z[1]*Z[1] + Z[2]*Z[2]);
        float cn[3][3];
        for (int d = 0; d < 3; d++) {
            cn[0][d] = X[d] / nx;
            cn[1][d] = Y[d] / ny;
            cn[2][d] = Z[d] / nz;
        }
        for (int k = 0; k < 3; k++)
            for (int d = 0; d < 3; d++)
                g_consts[12 + v * 12 + k * 3 + d] = cn[k][d];
        for (int d = 0; d < 3; d++)
            g_consts[12 + v * 12 + 9 + d] = Z[d];

        if (v == 0) {
            // A = c0^T ; Minv = inv(A), adjugate in double (one thread, ~2k cyc)
            double A[3][3];
            for (int i = 0; i < 3; i++)
                for (int j = 0; j < 3; j++)
                    A[i][j] = (double)cn[j][i];
            double det = A[0][0] * (A[1][1]*A[2][2] - A[1][2]*A[2][1])
                       + A[0][1] * (A[1][2]*A[2][0] - A[1][0]*A[2][2])
                       + A[0][2] * (A[1][0]*A[2][1] - A[1][1]*A[2][0]);
            double inv[3][3];
            inv[0][0] = (A[1][1]*A[2][2] - A[1][2]*A[2][1]) / det;
            inv[0][1] = (A[0][2]*A[2][1] - A[0][1]*A[2][2]) / det;
            inv[0][2] = (A[0][1]*A[1][2] - A[0][2]*A[1][1]) / det;
            inv[1][0] = (A[1][2]*A[2][0] - A[1][0]*A[2][2]) / det;
            inv[1][1] = (A[0][0]*A[2][2] - A[0][2]*A[2][0]) / det;
            inv[1][2] = (A[0][2]*A[1][0] - A[0][0]*A[1][2]) / det;
            inv[2][0] = (A[1][0]*A[2][1] - A[1][1]*A[2][0]) / det;
            inv[2][1] = (A[0][1]*A[2][0] - A[0][0]*A[2][1]) / det;
            inv[2][2] = (A[0][0]*A[1][1] - A[0][1]*A[1][0]) / det;
            for (int d = 0; d < 3; d++)
                for (int k = 0; k < 3; k++)
                    g_consts[d * 3 + k] = (float)inv[d][k];
            for (int d = 0; d < 3; d++)
                g_consts[9 + d] = Z[d];
        }
    }

    // --- feature transpose [C,H,W] -> [H,W,C] into scratch ---
    int i = blockIdx.x * blockDim.x + threadIdx.x;
    if (i >= 376320) return;
    float v;
    if (i < 200704)      { int c = i & 63;  int p = i >> 6;                 v = f0[c * 3136 + p]; }
    else if (i < 301056) { int l = i - 200704; int c = l & 127; int p = l >> 7; v = f1[c * 784 + p]; }
    else if (i < 351232) { int l = i - 301056; int c = l & 255; int p = l >> 8; v = f2[c * 196 + p]; }
    else                 { int l = i - 351232; int c = l & 511; int p = l >> 9; v = f3[c * 49 + p]; }
    g_scratch[i] = v;
}

__global__ __launch_bounds__(256) void main_kernel(const float* __restrict__ inputs,
                                                   float* __restrict__ out) {
    __shared__ int sbase[3][4];
    int row = blockIdx.x;
    int tid = threadIdx.x;

    if (tid < 3) {
        int v = tid;
        float in0 = inputs[row * 3 + 0];
        float in1 = inputs[row * 3 + 1];
        float in2 = inputs[row * 3 + 2];
        const float* C = g_consts;
        float po[3];
        #pragma unroll
        for (int k = 0; k < 3; k++)
            po[k] = fmaf(in0, C[0 * 3 + k],
                    fmaf(in1, C[1 * 3 + k],
                    fmaf(in2, C[2 * 3 + k], C[9 + k])));
        const float* cv = C + 12 + v * 12;
        float d0 = po[0] - cv[9];
        float d1 = po[1] - cv[10];
        float d2 = po[2] - cv[11];
        float X = fmaf(d0, cv[0], fmaf(d1, cv[1], d2 * cv[2]));
        float Y = fmaf(d0, cv[3], fmaf(d1, cv[4], d2 * cv[5]));
        float Z = fmaf(d0, cv[6], fmaf(d1, cv[7], d2 * cv[8]));
        float nz = -Z;
        float h = fmaf(248.0f, __fdiv_rn(-Y, nz), 112.0f);
        float w = fmaf(248.0f, __fdiv_rn(X, nz), 112.0f);
        if (isnan(h)) h = 0.0f;
        if (isnan(w)) w = 0.0f;
        h = fminf(fmaxf(h, 0.0f), 223.0f);
        w = fminf(fmaxf(w, 0.0f), 223.0f);
        // exact power-of-two scaling == reference's exact divisions
        int h0 = (int)(h * 0.25f),    w0 = (int)(w * 0.25f);
        int h1 = (int)(h * 0.125f),   w1 = (int)(w * 0.125f);
        int h2 = (int)(h * 0.0625f),  w2 = (int)(w * 0.0625f);
        int h3 = (int)(h * 0.03125f), w3 = (int)(w * 0.03125f);
        sbase[v][0] = (h0 * 56 + w0) * 64;
        sbase[v][1] = 200704 + (h1 * 28 + w1) * 128;
        sbase[v][2] = 301056 + (h2 * 14 + w2) * 256;
        sbase[v][3] = 351232 + (h3 * 7 + w3) * 512;
        __stcs(&out[(size_t)row * OUT_COLS + v], (v == 0) ? in0 : (v == 1) ? in1 : in2);
    }
    __syncthreads();

    int b00 = sbase[0][0], b01 = sbase[0][1], b02 = sbase[0][2], b03 = sbase[0][3];
    int b10 = sbase[1][0], b11 = sbase[1][1], b12 = sbase[1][2], b13 = sbase[1][3];
    int b20 = sbase[2][0], b21 = sbase[2][1], b22 = sbase[2][2], b23 = sbase[2][3];

    float* omax = out + (size_t)row * OUT_COLS + 3;

    #pragma unroll
    for (int it = 0; it < 4; it++) {
        int c = tid + it * 256;
        if (c >= 960) break;
        int i0, i1, i2;
        if (c < 64)       { i0 = b00 + c;       i1 = b10 + c;       i2 = b20 + c; }
        else if (c < 192) { int l = c - 64;  i0 = b01 + l; i1 = b11 + l; i2 = b21 + l; }
        else if (c < 448) { int l = c - 192; i0 = b02 + l; i1 = b12 + l; i2 = b22 + l; }
        else              { int l = c - 448; i0 = b03 + l; i1 = b13 + l; i2 = b23 + l; }
        float a = __ldg(&g_scratch[i0]);
        float b = __ldg(&g_scratch[i1]);
        float d = __ldg(&g_scratch[i2]);
        float mx = fmaxf(a, fmaxf(b, d));
        float mn = (a + b + d) * (1.0f / 3.0f);
        float e0 = a - mn, e1 = b - mn, e2 = d - mn;
        float sd = sqrtf((e0 * e0 + e1 * e1 + e2 * e2) * (1.0f / 3.0f));
        __stcs(&omax[c], mx);
        __stcs(&omax[960 + c], mn);
        __stcs(&omax[1920 + c], sd);
    }
}

extern "C" void kernel_launch(void* const* d_in, const int* in_sizes, int n_in,
                              void* d_out, int out_size) {
    const float* inputs  = (const float*)d_in[0];
    const float* cameras = (const float*)d_in[1];
    const float* f0 = (const float*)d_in[2];
    const float* f1 = (const float*)d_in[3];
    const float* f2 = (const float*)d_in[4];
    const float* f3 = (const float*)d_in[5];
    float* out = (float*)d_out;

    int n = in_sizes[0] / 3;

    prep_kernel<<<(376320 + 255) / 256, 256>>>(f0, f1, f2, f3, cameras);
    main_kernel<<<n, 256>>>(inputs, out);
}